// round 9
// baseline (speedup 1.0000x reference)
#include <cuda_runtime.h>
#include <cstdint>

#define ADAPT  32
#define T_LEN  2048
#define NCH    (T_LEN / ADAPT)    // 64 chunks per batch row

// Streaming 128-bit load with 256B L2 fetch-granularity hint
__device__ __forceinline__ float4 ldcs_256B(const float4* p) {
    float4 q;
    asm volatile("ld.global.cs.L2::256B.v4.f32 {%0,%1,%2,%3}, [%4];"
                 : "=f"(q.x), "=f"(q.y), "=f"(q.z), "=f"(q.w)
                 : "l"(p));
    return q;
}
// L2 prefetch at [p + 49152B] (12 chunks ahead) — reg+imm, no extra live regs
__device__ __forceinline__ void l2_prefetch_12ch(const float4* p) {
    asm volatile("prefetch.global.L2 [%0+49152];" :: "l"(p));
}

// ---------------------------------------------------------------------------
// One block (256 threads) per batch row, 8 blocks/SM (regs must stay <= 32).
//  Phase A: thread t <-> (step s = t>>3, bin-quad j = t&7). Per chunk:
//    one coalesced streaming LDG.128 (+256B L2 granule hint). One thread per
//    128B line (j==0) issues a 48KB-ahead L2 prefetch to keep the DRAM
//    scheduler window deep. Then dot vs qb4[j]/cs4[j] and two INDEPENDENT
//    3-step octet shfl chains (p and g, ILP=2) -> s_dot / s_g.
//  Phase B: per-chunk means, then warp-0 affine scan of the 64-chunk
//    recurrence (S,P) -> (S*mg, P + S*mdot).
//  Phase C: out = P[c] + S[c]*dot, vectorized float4, streaming stores.
// ---------------------------------------------------------------------------
__global__ void __launch_bounds__(256, 8)
fused_dequant(const float4* __restrict__ x4,
              const float*  __restrict__ qb,
              const float*  __restrict__ cs,
              float*        __restrict__ out)
{
    __shared__ float s_dot[T_LEN];          // 8 KB
    __shared__ float s_g  [T_LEN];          // 8 KB
    __shared__ float s_md[NCH], s_mg[NCH];
    __shared__ float sP[NCH], sS[NCH];

    const int tid  = threadIdx.x;
    const int lane = tid & 31;
    const int w    = tid >> 5;
    const int j    = tid & 7;      // bin quad
    const int srow = tid >> 3;     // step within chunk (0..31)
    const int b    = blockIdx.x;

    const float4 b4 = reinterpret_cast<const float4*>(qb)[j];
    const float4 c4 = reinterpret_cast<const float4*>(cs)[j];

    // batch row = 2048*32 floats = 16384 float4; chunk = 256 float4
    const float4* xb = x4 + (size_t)b * 16384;

    // ---- Phase A ----
#pragma unroll 2
    for (int c = 0; c < NCH; c++) {
        const float4* ap = &xb[c * 256 + tid];
        const float4 q = ldcs_256B(ap);              // evict-first stream
        // one prefetch per 128B line, 12 chunks (48 KB) ahead
        if (j == 0 && c + 12 < NCH) l2_prefetch_12ch(ap);

        float p = q.x * b4.x + q.y * b4.y + q.z * b4.z + q.w * b4.w;
        float g = q.x * c4.x + q.y * c4.y + q.z * c4.z + q.w * c4.w;
        // two independent 3-deep chains (ILP = 2)
        p += __shfl_xor_sync(0xffffffffu, p, 1);
        g += __shfl_xor_sync(0xffffffffu, g, 1);
        p += __shfl_xor_sync(0xffffffffu, p, 2);
        g += __shfl_xor_sync(0xffffffffu, g, 2);
        p += __shfl_xor_sync(0xffffffffu, p, 4);
        g += __shfl_xor_sync(0xffffffffu, g, 4);
        if (j == 0) {
            s_dot[c * 32 + srow] = p;
            s_g  [c * 32 + srow] = g;
        }
    }
    __syncthreads();

    // ---- Phase B1: per-chunk means (warp w handles chunks 8w..8w+7) ----
#pragma unroll
    for (int i = 0; i < 8; i++) {
        const int c = w * 8 + i;
        float md = s_dot[c * 32 + lane];
        float mg = s_g  [c * 32 + lane];
#pragma unroll
        for (int off = 16; off; off >>= 1) {
            md += __shfl_xor_sync(0xffffffffu, md, off);
            mg += __shfl_xor_sync(0xffffffffu, mg, off);
        }
        if (lane == 0) {
            s_md[c] = md * (1.f / ADAPT);
            s_mg[c] = mg * (1.f / ADAPT);
        }
    }
    __syncthreads();

    // ---- Phase B2: affine scan of 64 chunks in warp 0 (2 chunks/lane) ----
    if (tid < 32) {
        const float md0 = s_md[2 * lane], md1 = s_md[2 * lane + 1];
        const float mg0 = s_mg[2 * lane], mg1 = s_mg[2 * lane + 1];

        float g = mg0 * mg1;            // segment: (S,P)->(S*g, P+S*d)
        float d = md0 + mg0 * md1;
#pragma unroll
        for (int off = 1; off < 32; off <<= 1) {
            const float gp = __shfl_up_sync(0xffffffffu, g, off);
            const float dp = __shfl_up_sync(0xffffffffu, d, off);
            if (lane >= off) { d = dp + gp * d; g = gp * g; }
        }
        float Se = __shfl_up_sync(0xffffffffu, g, 1);
        float Pe = __shfl_up_sync(0xffffffffu, d, 1);
        if (lane == 0) { Se = 1.f; Pe = 0.f; }

        sS[2 * lane]     = Se;
        sP[2 * lane]     = Pe;
        sS[2 * lane + 1] = Se * mg0;
        sP[2 * lane + 1] = Pe + Se * md0;
    }
    __syncthreads();

    // ---- Phase C: vectorized output, streaming stores ----
    const float4* sd4 = reinterpret_cast<const float4*>(s_dot);
    float4* ob4 = reinterpret_cast<float4*>(out + (size_t)b * T_LEN);
#pragma unroll
    for (int k = 0; k < 2; k++) {
        const int u4 = k * 256 + tid;   // float4 index within row (0..511)
        const int c  = u4 >> 3;         // 8 float4 per chunk
        const float P = sP[c];
        const float S = sS[c];
        const float4 q = sd4[u4];
        const float4 o = make_float4(P + S * q.x, P + S * q.y,
                                     P + S * q.z, P + S * q.w);
        __stcs(&ob4[u4], o);
    }
}

// ---------------------------------------------------------------------------
extern "C" void kernel_launch(void* const* d_in, const int* in_sizes, int n_in,
                              void* d_out, int out_size)
{
    const float* x  = (const float*)d_in[0];   // (B, T, NB) fp32
    const float* qb = (const float*)d_in[1];   // (NB,)
    const float* cs = (const float*)d_in[2];   // (NB, 1)
    float* out      = (float*)d_out;           // (B, T) fp32

    const int B = out_size / T_LEN;
    fused_dequant<<<B, 256>>>(reinterpret_cast<const float4*>(x), qb, cs, out);
}

// round 10
// speedup vs baseline: 1.0463x; 1.0463x over previous
#include <cuda_runtime.h>
#include <cstdint>

#define ADAPT  32
#define T_LEN  2048
#define NCH    (T_LEN / ADAPT)    // 64 chunks per batch row

// Streaming 128-bit load with 256B L2 fetch-granularity hint
__device__ __forceinline__ float4 ldcs_256B(const float4* p) {
    float4 q;
    asm volatile("ld.global.cs.L2::256B.v4.f32 {%0,%1,%2,%3}, [%4];"
                 : "=f"(q.x), "=f"(q.y), "=f"(q.z), "=f"(q.w)
                 : "l"(p));
    return q;
}
// L2 prefetch at [p + 32768B] (8 chunks ahead) — reg+imm, no extra live regs
__device__ __forceinline__ void l2_prefetch_8ch(const float4* p) {
    asm volatile("prefetch.global.L2 [%0+32768];" :: "l"(p));
}

// ---------------------------------------------------------------------------
// One block (256 threads) per batch row, 8 blocks/SM (regs must stay <= 32).
//  Phase A: thread t <-> (step s = t>>3, bin-quad j = t&7). Per chunk:
//    one coalesced streaming LDG.128 (+256B L2 granule hint, +32KB L2
//    prefetch from every thread), dot vs qb4[j]/cs4[j], two INDEPENDENT
//    3-step octet shfl chains (p and g, ILP=2) -> s_dot / s_g.
//  Phase B: per-chunk means, then warp-0 affine scan of the 64-chunk
//    recurrence (S,P) -> (S*mg, P + S*mdot).
//  Phase C: out = P[c] + S[c]*dot, vectorized float4, streaming stores.
// ---------------------------------------------------------------------------
__global__ void __launch_bounds__(256, 8)
fused_dequant(const float4* __restrict__ x4,
              const float*  __restrict__ qb,
              const float*  __restrict__ cs,
              float*        __restrict__ out)
{
    __shared__ float s_dot[T_LEN];          // 8 KB
    __shared__ float s_g  [T_LEN];          // 8 KB
    __shared__ float s_md[NCH], s_mg[NCH];
    __shared__ float sP[NCH], sS[NCH];

    const int tid  = threadIdx.x;
    const int lane = tid & 31;
    const int w    = tid >> 5;
    const int j    = tid & 7;      // bin quad
    const int srow = tid >> 3;     // step within chunk (0..31)
    const int b    = blockIdx.x;

    const float4 b4 = reinterpret_cast<const float4*>(qb)[j];
    const float4 c4 = reinterpret_cast<const float4*>(cs)[j];

    // batch row = 2048*32 floats = 16384 float4; chunk = 256 float4
    const float4* xb = x4 + (size_t)b * 16384;

    // ---- Phase A ----
#pragma unroll 2
    for (int c = 0; c < NCH; c++) {
        const float4* ap = &xb[c * 256 + tid];
        const float4 q = ldcs_256B(ap);              // evict-first stream
        if (c + 8 < NCH) l2_prefetch_8ch(ap);        // deepen DRAM window

        float p = q.x * b4.x + q.y * b4.y + q.z * b4.z + q.w * b4.w;
        float g = q.x * c4.x + q.y * c4.y + q.z * c4.z + q.w * c4.w;
        // two independent 3-deep chains (ILP = 2)
        p += __shfl_xor_sync(0xffffffffu, p, 1);
        g += __shfl_xor_sync(0xffffffffu, g, 1);
        p += __shfl_xor_sync(0xffffffffu, p, 2);
        g += __shfl_xor_sync(0xffffffffu, g, 2);
        p += __shfl_xor_sync(0xffffffffu, p, 4);
        g += __shfl_xor_sync(0xffffffffu, g, 4);
        if (j == 0) {
            s_dot[c * 32 + srow] = p;
            s_g  [c * 32 + srow] = g;
        }
    }
    __syncthreads();

    // ---- Phase B1: per-chunk means (warp w handles chunks 8w..8w+7) ----
#pragma unroll
    for (int i = 0; i < 8; i++) {
        const int c = w * 8 + i;
        float md = s_dot[c * 32 + lane];
        float mg = s_g  [c * 32 + lane];
#pragma unroll
        for (int off = 16; off; off >>= 1) {
            md += __shfl_xor_sync(0xffffffffu, md, off);
            mg += __shfl_xor_sync(0xffffffffu, mg, off);
        }
        if (lane == 0) {
            s_md[c] = md * (1.f / ADAPT);
            s_mg[c] = mg * (1.f / ADAPT);
        }
    }
    __syncthreads();

    // ---- Phase B2: affine scan of 64 chunks in warp 0 (2 chunks/lane) ----
    if (tid < 32) {
        const float md0 = s_md[2 * lane], md1 = s_md[2 * lane + 1];
        const float mg0 = s_mg[2 * lane], mg1 = s_mg[2 * lane + 1];

        float g = mg0 * mg1;            // segment: (S,P)->(S*g, P+S*d)
        float d = md0 + mg0 * md1;
#pragma unroll
        for (int off = 1; off < 32; off <<= 1) {
            const float gp = __shfl_up_sync(0xffffffffu, g, off);
            const float dp = __shfl_up_sync(0xffffffffu, d, off);
            if (lane >= off) { d = dp + gp * d; g = gp * g; }
        }
        float Se = __shfl_up_sync(0xffffffffu, g, 1);
        float Pe = __shfl_up_sync(0xffffffffu, d, 1);
        if (lane == 0) { Se = 1.f; Pe = 0.f; }

        sS[2 * lane]     = Se;
        sP[2 * lane]     = Pe;
        sS[2 * lane + 1] = Se * mg0;
        sP[2 * lane + 1] = Pe + Se * md0;
    }
    __syncthreads();

    // ---- Phase C: vectorized output, streaming stores ----
    const float4* sd4 = reinterpret_cast<const float4*>(s_dot);
    float4* ob4 = reinterpret_cast<float4*>(out + (size_t)b * T_LEN);
#pragma unroll
    for (int k = 0; k < 2; k++) {
        const int u4 = k * 256 + tid;   // float4 index within row (0..511)
        const int c  = u4 >> 3;         // 8 float4 per chunk
        const float P = sP[c];
        const float S = sS[c];
        const float4 q = sd4[u4];
        const float4 o = make_float4(P + S * q.x, P + S * q.y,
                                     P + S * q.z, P + S * q.w);
        __stcs(&ob4[u4], o);
    }
}

// ---------------------------------------------------------------------------
extern "C" void kernel_launch(void* const* d_in, const int* in_sizes, int n_in,
                              void* d_out, int out_size)
{
    const float* x  = (const float*)d_in[0];   // (B, T, NB) fp32
    const float* qb = (const float*)d_in[1];   // (NB,)
    const float* cs = (const float*)d_in[2];   // (NB, 1)
    float* out      = (float*)d_out;           // (B, T) fp32

    const int B = out_size / T_LEN;
    fused_dequant<<<B, 256>>>(reinterpret_cast<const float4*>(x), qb, cs, out);
}

// round 11
// speedup vs baseline: 1.0513x; 1.0048x over previous
#include <cuda_runtime.h>
#include <cstdint>

#define ADAPT  32
#define T_LEN  2048
#define NCH    (T_LEN / ADAPT)    // 64 chunks per batch row

// Streaming 128-bit load with 256B L2 fetch-granularity hint
__device__ __forceinline__ float4 ldcs_256B(const float4* p) {
    float4 q;
    asm volatile("ld.global.cs.L2::256B.v4.f32 {%0,%1,%2,%3}, [%4];"
                 : "=f"(q.x), "=f"(q.y), "=f"(q.z), "=f"(q.w)
                 : "l"(p));
    return q;
}
// L2 prefetch at [p + 24576B] (6 chunks ahead) — reg+imm, no extra live regs
__device__ __forceinline__ void l2_prefetch_6ch(const float4* p) {
    asm volatile("prefetch.global.L2 [%0+24576];" :: "l"(p));
}

// ---------------------------------------------------------------------------
// One block (256 threads) per batch row, 8 blocks/SM (regs must stay <= 32).
// Measured optimum config (R8): 24KB all-thread L2 prefetch window.
//  Phase A: thread t <-> (step s = t>>3, bin-quad j = t&7). Per chunk:
//    one coalesced streaming LDG.128 (+256B L2 granule hint, +24KB L2
//    prefetch from every thread), dot vs qb4[j]/cs4[j], two INDEPENDENT
//    3-step octet shfl chains (p and g, ILP=2) -> s_dot / s_g.
//  Phase B: per-chunk means, then warp-0 affine scan of the 64-chunk
//    recurrence (S,P) -> (S*mg, P + S*mdot).
//  Phase C: out = P[c] + S[c]*dot, vectorized float4, streaming stores.
// ---------------------------------------------------------------------------
__global__ void __launch_bounds__(256, 8)
fused_dequant(const float4* __restrict__ x4,
              const float*  __restrict__ qb,
              const float*  __restrict__ cs,
              float*        __restrict__ out)
{
    __shared__ float s_dot[T_LEN];          // 8 KB
    __shared__ float s_g  [T_LEN];          // 8 KB
    __shared__ float s_md[NCH], s_mg[NCH];
    __shared__ float sP[NCH], sS[NCH];

    const int tid  = threadIdx.x;
    const int lane = tid & 31;
    const int w    = tid >> 5;
    const int j    = tid & 7;      // bin quad
    const int srow = tid >> 3;     // step within chunk (0..31)
    const int b    = blockIdx.x;

    const float4 b4 = reinterpret_cast<const float4*>(qb)[j];
    const float4 c4 = reinterpret_cast<const float4*>(cs)[j];

    // batch row = 2048*32 floats = 16384 float4; chunk = 256 float4
    const float4* xb = x4 + (size_t)b * 16384;

    // ---- Phase A ----
#pragma unroll 2
    for (int c = 0; c < NCH; c++) {
        const float4* ap = &xb[c * 256 + tid];
        const float4 q = ldcs_256B(ap);              // evict-first stream
        if (c + 6 < NCH) l2_prefetch_6ch(ap);        // deepen DRAM window

        float p = q.x * b4.x + q.y * b4.y + q.z * b4.z + q.w * b4.w;
        float g = q.x * c4.x + q.y * c4.y + q.z * c4.z + q.w * c4.w;
        // two independent 3-deep chains (ILP = 2)
        p += __shfl_xor_sync(0xffffffffu, p, 1);
        g += __shfl_xor_sync(0xffffffffu, g, 1);
        p += __shfl_xor_sync(0xffffffffu, p, 2);
        g += __shfl_xor_sync(0xffffffffu, g, 2);
        p += __shfl_xor_sync(0xffffffffu, p, 4);
        g += __shfl_xor_sync(0xffffffffu, g, 4);
        if (j == 0) {
            s_dot[c * 32 + srow] = p;
            s_g  [c * 32 + srow] = g;
        }
    }
    __syncthreads();

    // ---- Phase B1: per-chunk means (warp w handles chunks 8w..8w+7) ----
#pragma unroll
    for (int i = 0; i < 8; i++) {
        const int c = w * 8 + i;
        float md = s_dot[c * 32 + lane];
        float mg = s_g  [c * 32 + lane];
#pragma unroll
        for (int off = 16; off; off >>= 1) {
            md += __shfl_xor_sync(0xffffffffu, md, off);
            mg += __shfl_xor_sync(0xffffffffu, mg, off);
        }
        if (lane == 0) {
            s_md[c] = md * (1.f / ADAPT);
            s_mg[c] = mg * (1.f / ADAPT);
        }
    }
    __syncthreads();

    // ---- Phase B2: affine scan of 64 chunks in warp 0 (2 chunks/lane) ----
    if (tid < 32) {
        const float md0 = s_md[2 * lane], md1 = s_md[2 * lane + 1];
        const float mg0 = s_mg[2 * lane], mg1 = s_mg[2 * lane + 1];

        float g = mg0 * mg1;            // segment: (S,P)->(S*g, P+S*d)
        float d = md0 + mg0 * md1;
#pragma unroll
        for (int off = 1; off < 32; off <<= 1) {
            const float gp = __shfl_up_sync(0xffffffffu, g, off);
            const float dp = __shfl_up_sync(0xffffffffu, d, off);
            if (lane >= off) { d = dp + gp * d; g = gp * g; }
        }
        float Se = __shfl_up_sync(0xffffffffu, g, 1);
        float Pe = __shfl_up_sync(0xffffffffu, d, 1);
        if (lane == 0) { Se = 1.f; Pe = 0.f; }

        sS[2 * lane]     = Se;
        sP[2 * lane]     = Pe;
        sS[2 * lane + 1] = Se * mg0;
        sP[2 * lane + 1] = Pe + Se * md0;
    }
    __syncthreads();

    // ---- Phase C: vectorized output, streaming stores ----
    const float4* sd4 = reinterpret_cast<const float4*>(s_dot);
    float4* ob4 = reinterpret_cast<float4*>(out + (size_t)b * T_LEN);
#pragma unroll
    for (int k = 0; k < 2; k++) {
        const int u4 = k * 256 + tid;   // float4 index within row (0..511)
        const int c  = u4 >> 3;         // 8 float4 per chunk
        const float P = sP[c];
        const float S = sS[c];
        const float4 q = sd4[u4];
        const float4 o = make_float4(P + S * q.x, P + S * q.y,
                                     P + S * q.z, P + S * q.w);
        __stcs(&ob4[u4], o);
    }
}

// ---------------------------------------------------------------------------
extern "C" void kernel_launch(void* const* d_in, const int* in_sizes, int n_in,
                              void* d_out, int out_size)
{
    const float* x  = (const float*)d_in[0];   // (B, T, NB) fp32
    const float* qb = (const float*)d_in[1];   // (NB,)
    const float* cs = (const float*)d_in[2];   // (NB, 1)
    float* out      = (float*)d_out;           // (B, T) fp32

    const int B = out_size / T_LEN;
    fused_dequant<<<B, 256>>>(reinterpret_cast<const float4*>(x), qb, cs, out);
}

// round 12
// speedup vs baseline: 1.0940x; 1.0406x over previous
#include <cuda_runtime.h>
#include <cstdint>

#define ADAPT  32
#define T_LEN  2048
#define NCH    (T_LEN / ADAPT)    // 64 chunks per batch row

// Streaming 128-bit load with 256B L2 fetch-granularity hint
__device__ __forceinline__ float4 ldcs_256B(const float4* p) {
    float4 q;
    asm volatile("ld.global.cs.L2::256B.v4.f32 {%0,%1,%2,%3}, [%4];"
                 : "=f"(q.x), "=f"(q.y), "=f"(q.z), "=f"(q.w)
                 : "l"(p));
    return q;
}
// L2 prefetch at [p + 24576B] (6 chunks ahead) — reg+imm, no extra live regs
__device__ __forceinline__ void l2_prefetch_6ch(const float4* p) {
    asm volatile("prefetch.global.L2 [%0+24576];" :: "l"(p));
}

// ---------------------------------------------------------------------------
// One block (256 threads) per batch row, 8 blocks/SM (regs must stay <= 32).
// R8-optimum config + software-pipelined demand load: chunk c+1's LDG is
// issued BEFORE chunk c's dependent shuffle chain, guaranteeing one load
// always in flight ahead of the math.
//  Phase A: thread t <-> (step s = t>>3, bin-quad j = t&7); streaming
//    LDG.128 (+256B L2 granule, +24KB all-thread L2 prefetch), dot vs
//    qb4[j]/cs4[j], two independent 3-step octet shfl chains -> s_dot/s_g.
//  Phase B: per-chunk means, then warp-0 affine scan of the 64-chunk
//    recurrence (S,P) -> (S*mg, P + S*mdot).
//  Phase C: out = P[c] + S[c]*dot, vectorized float4, streaming stores.
// ---------------------------------------------------------------------------
__global__ void __launch_bounds__(256, 8)
fused_dequant(const float4* __restrict__ x4,
              const float*  __restrict__ qb,
              const float*  __restrict__ cs,
              float*        __restrict__ out)
{
    __shared__ float s_dot[T_LEN];          // 8 KB
    __shared__ float s_g  [T_LEN];          // 8 KB
    __shared__ float s_md[NCH], s_mg[NCH];
    __shared__ float sP[NCH], sS[NCH];

    const int tid  = threadIdx.x;
    const int lane = tid & 31;
    const int w    = tid >> 5;
    const int j    = tid & 7;      // bin quad
    const int srow = tid >> 3;     // step within chunk (0..31)
    const int b    = blockIdx.x;

    const float4 b4 = reinterpret_cast<const float4*>(qb)[j];
    const float4 c4 = reinterpret_cast<const float4*>(cs)[j];

    // batch row = 2048*32 floats = 16384 float4; chunk = 256 float4
    const float4* xb = x4 + (size_t)b * 16384;

    // ---- Phase A: rotated 1-deep pipeline ----
    float4 q = ldcs_256B(&xb[tid]);          // chunk 0 in flight
#pragma unroll 2
    for (int c = 0; c < NCH; c++) {
        const float4* ap = &xb[c * 256 + tid];
        if (c + 6 < NCH) l2_prefetch_6ch(ap);          // deepen DRAM window
        // issue next chunk's demand load BEFORE consuming current data
        float4 qn;
        if (c + 1 < NCH) qn = ldcs_256B(ap + 256);

        float p = q.x * b4.x + q.y * b4.y + q.z * b4.z + q.w * b4.w;
        float g = q.x * c4.x + q.y * c4.y + q.z * c4.z + q.w * c4.w;
        // two independent 3-deep chains (ILP = 2)
        p += __shfl_xor_sync(0xffffffffu, p, 1);
        g += __shfl_xor_sync(0xffffffffu, g, 1);
        p += __shfl_xor_sync(0xffffffffu, p, 2);
        g += __shfl_xor_sync(0xffffffffu, g, 2);
        p += __shfl_xor_sync(0xffffffffu, p, 4);
        g += __shfl_xor_sync(0xffffffffu, g, 4);
        if (j == 0) {
            s_dot[c * 32 + srow] = p;
            s_g  [c * 32 + srow] = g;
        }
        q = qn;
    }
    __syncthreads();

    // ---- Phase B1: per-chunk means (warp w handles chunks 8w..8w+7) ----
#pragma unroll
    for (int i = 0; i < 8; i++) {
        const int c = w * 8 + i;
        float md = s_dot[c * 32 + lane];
        float mg = s_g  [c * 32 + lane];
#pragma unroll
        for (int off = 16; off; off >>= 1) {
            md += __shfl_xor_sync(0xffffffffu, md, off);
            mg += __shfl_xor_sync(0xffffffffu, mg, off);
        }
        if (lane == 0) {
            s_md[c] = md * (1.f / ADAPT);
            s_mg[c] = mg * (1.f / ADAPT);
        }
    }
    __syncthreads();

    // ---- Phase B2: affine scan of 64 chunks in warp 0 (2 chunks/lane) ----
    if (tid < 32) {
        const float md0 = s_md[2 * lane], md1 = s_md[2 * lane + 1];
        const float mg0 = s_mg[2 * lane], mg1 = s_mg[2 * lane + 1];

        float g = mg0 * mg1;            // segment: (S,P)->(S*g, P+S*d)
        float d = md0 + mg0 * md1;
#pragma unroll
        for (int off = 1; off < 32; off <<= 1) {
            const float gp = __shfl_up_sync(0xffffffffu, g, off);
            const float dp = __shfl_up_sync(0xffffffffu, d, off);
            if (lane >= off) { d = dp + gp * d; g = gp * g; }
        }
        float Se = __shfl_up_sync(0xffffffffu, g, 1);
        float Pe = __shfl_up_sync(0xffffffffu, d, 1);
        if (lane == 0) { Se = 1.f; Pe = 0.f; }

        sS[2 * lane]     = Se;
        sP[2 * lane]     = Pe;
        sS[2 * lane + 1] = Se * mg0;
        sP[2 * lane + 1] = Pe + Se * md0;
    }
    __syncthreads();

    // ---- Phase C: vectorized output, streaming stores ----
    const float4* sd4 = reinterpret_cast<const float4*>(s_dot);
    float4* ob4 = reinterpret_cast<float4*>(out + (size_t)b * T_LEN);
#pragma unroll
    for (int k = 0; k < 2; k++) {
        const int u4 = k * 256 + tid;   // float4 index within row (0..511)
        const int c  = u4 >> 3;         // 8 float4 per chunk
        const float P = sP[c];
        const float S = sS[c];
        const float4 qv = sd4[u4];
        const float4 o = make_float4(P + S * qv.x, P + S * qv.y,
                                     P + S * qv.z, P + S * qv.w);
        __stcs(&ob4[u4], o);
    }
}

// ---------------------------------------------------------------------------
extern "C" void kernel_launch(void* const* d_in, const int* in_sizes, int n_in,
                              void* d_out, int out_size)
{
    const float* x  = (const float*)d_in[0];   // (B, T, NB) fp32
    const float* qb = (const float*)d_in[1];   // (NB,)
    const float* cs = (const float*)d_in[2];   // (NB, 1)
    float* out      = (float*)d_out;           // (B, T) fp32

    const int B = out_size / T_LEN;
    fused_dequant<<<B, 256>>>(reinterpret_cast<const float4*>(x), qb, cs, out);
}